// round 16
// baseline (speedup 1.0000x reference)
#include <cuda_runtime.h>
#include <cuda_bf16.h>
#include <math.h>

#define BH 32
#define NSEQ 4096
#define DDIM 64
#define MDIM 266
#define MPAD 272            // dash row stride (floats)
#define ECOLS 65
#define EROWS 68
#define NPAD 288            // dash mma n-dim padding
#define BROW 144            // dash bf16 smem row stride BYTES
#define NORMALIZER 0.3535533905932738f   // 64^-0.25
#define DIAGC 0.0625f                    // 0.5 * 64^-0.5
#define KEPS 1e-4f
#define RATIO 0.06131393835f             // 266^-0.5

// ---------------- warp-mma helpers (non-'a' features) --------------
__device__ __forceinline__ unsigned int smem_u32(const void* p) {
    unsigned int a;
    asm("{ .reg .u64 t; cvta.to.shared.u64 t, %1; cvt.u32.u64 %0, t; }" : "=r"(a) : "l"(p));
    return a;
}
#define LDM_X4(d, addr) \
    asm volatile("ldmatrix.sync.aligned.m8n8.x4.shared.b16 {%0,%1,%2,%3}, [%4];" \
        : "=r"((d)[0]), "=r"((d)[1]), "=r"((d)[2]), "=r"((d)[3]) : "r"(addr))
#define LDM_X2(d0, d1, addr) \
    asm volatile("ldmatrix.sync.aligned.m8n8.x2.shared.b16 {%0,%1}, [%2];" \
        : "=r"(d0), "=r"(d1) : "r"(addr))
#define LDM_X4T(d, addr) \
    asm volatile("ldmatrix.sync.aligned.m8n8.x4.trans.shared.b16 {%0,%1,%2,%3}, [%4];" \
        : "=r"((d)[0]), "=r"((d)[1]), "=r"((d)[2]), "=r"((d)[3]) : "r"(addr))
#define LDM_X2T(d0, d1, addr) \
    asm volatile("ldmatrix.sync.aligned.m8n8.x2.trans.shared.b16 {%0,%1}, [%2];" \
        : "=r"(d0), "=r"(d1) : "r"(addr))
#define MMA_BF16(c, a, b0, b1) \
    asm volatile("mma.sync.aligned.m16n8k16.row.col.f32.bf16.bf16.f32 " \
        "{%0,%1,%2,%3}, {%4,%5,%6,%7}, {%8,%9}, {%0,%1,%2,%3};" \
        : "+f"((c)[0]), "+f"((c)[1]), "+f"((c)[2]), "+f"((c)[3]) \
        : "r"((a)[0]), "r"((a)[1]), "r"((a)[2]), "r"((a)[3]), "r"(b0), "r"(b1))

__device__ __forceinline__ void split2(float x, float y, unsigned int& hi, unsigned int& lo) {
    __nv_bfloat16 hx = __float2bfloat16(x);
    __nv_bfloat16 hy = __float2bfloat16(y);
    float rx = x - __bfloat162float(hx);
    float ry = y - __bfloat162float(hy);
    hi = ((unsigned)__bfloat16_as_ushort(hy) << 16) | (unsigned)__bfloat16_as_ushort(hx);
    lo = ((unsigned)__bfloat16_as_ushort(__float2bfloat16(ry)) << 16)
       | (unsigned)__bfloat16_as_ushort(__float2bfloat16(rx));
}

// ---------------- scratch ----------------
__device__ unsigned int g_stab_bits;
__device__ float g_CT[(size_t)BH * EROWS * MPAD];        // [bh][e][m]
__device__ float g_kdash[(size_t)BH * NSEQ * MPAD];
__device__ float g_qdash[(size_t)BH * NSEQ * MPAD];
__device__ float g_kdiag[BH * NSEQ];
__device__ float g_qdiag[BH * NSEQ];

__device__ __forceinline__ unsigned int fenc(float f) {
    unsigned int b = __float_as_uint(f);
    return (b & 0x80000000u) ? ~b : (b | 0x80000000u);
}
__device__ __forceinline__ float fdec(unsigned int u) {
    return (u & 0x80000000u) ? __uint_as_float(u & 0x7FFFFFFFu) : __uint_as_float(~u);
}

__global__ void init_kernel() {
    int i = blockIdx.x * blockDim.x + threadIdx.x;
    if (i == 0) g_stab_bits = 0u;
    int stride = gridDim.x * blockDim.x;
    for (size_t idx = i; idx < (size_t)BH * EROWS * MPAD; idx += stride) g_CT[idx] = 0.0f;
}

// =======================================================================
// dash_mma (unchanged, R12-passing): dash = (NORM*X)@P^T, bf16x3 mma.
// 512 threads / 16 warps; rb-split; grid BH*4.
// =======================================================================
#define SM_AHI 0
#define SM_ALO (128 * BROW)
#define SM_PHI (2 * 128 * BROW)
#define SM_PLO (SM_PHI + NPAD * BROW)
#define SM_DASH_TOTAL (SM_PLO + NPAD * BROW)

__global__ void __launch_bounds__(512, 1)
dash_mma_kernel(const float* __restrict__ x, const float* __restrict__ proj, int isK) {
    extern __shared__ char smc[];
    unsigned int sb = smem_u32(smc);
    __shared__ unsigned int red;
    int tid = threadIdx.x, wid = tid >> 5, lid = tid & 31;
    int g = lid >> 2, tc = lid & 3;
    int bh = blockIdx.x >> 2, chunk = blockIdx.x & 3;
    if (tid == 0) red = 0u;

    {   // P split -> smem once (rows >= 266 zero)
        const float4* p4 = (const float4*)proj;
        for (int i = tid; i < NPAD * 16; i += 512) {
            int m = i >> 4, gg = i & 15;
            float4 v = (m < MDIM) ? p4[m * 16 + gg] : make_float4(0.f, 0.f, 0.f, 0.f);
            unsigned int h0, l0, h1, l1;
            split2(v.x, v.y, h0, l0);
            split2(v.z, v.w, h1, l1);
            *(uint2*)(smc + SM_PHI + m * BROW + gg * 8) = make_uint2(h0, h1);
            *(uint2*)(smc + SM_PLO + m * BROW + gg * 8) = make_uint2(l0, l1);
        }
    }

    const float* xbase = x + ((size_t)bh * NSEQ + chunk * 1024) * DDIM;
    float* dashp = isK ? g_kdash : g_qdash;
    float* diagp = isK ? g_kdiag : g_qdiag;
    float maxv = -INFINITY;

    int rg = wid & 3, ng = wid >> 2;
    int r0w = rg * 32;
    int n0w = ng * 72;
    int a_row = ((lid >> 3) & 1) * 8 + (lid & 7);
    int a_k8  = ((lid >> 4) & 1) * 8;
    int b_row = lid & 7;
    int b_k8  = ((lid >> 3) & 1) * 8;
    unsigned int bHiP = sb + SM_PHI + (unsigned)((n0w + b_row) * BROW + b_k8 * 2);
    unsigned int bLoP = bHiP + (SM_PLO - SM_PHI);

    for (int s = 0; s < 8; s++) {
        __syncthreads();
        {
            int row = tid >> 2, quarter = tid & 3;
            const float4* xsrc = (const float4*)(xbase + (size_t)s * 128 * DDIM);
            float ssum = 0.f;
#pragma unroll
            for (int j = 0; j < 4; j++) {
                float4 v = xsrc[row * 16 + quarter * 4 + j];
                ssum += v.x * v.x + v.y * v.y + v.z * v.z + v.w * v.w;
                unsigned int h0, l0, h1, l1;
                split2(v.x * NORMALIZER, v.y * NORMALIZER, h0, l0);
                split2(v.z * NORMALIZER, v.w * NORMALIZER, h1, l1);
                int gg = quarter * 4 + j;
                *(uint2*)(smc + SM_AHI + row * BROW + gg * 8) = make_uint2(h0, h1);
                *(uint2*)(smc + SM_ALO + row * BROW + gg * 8) = make_uint2(l0, l1);
            }
            ssum += __shfl_xor_sync(0xffffffffu, ssum, 1);
            ssum += __shfl_xor_sync(0xffffffffu, ssum, 2);
            if (quarter == 0)
                diagp[(size_t)bh * NSEQ + chunk * 1024 + s * 128 + row] = DIAGC * ssum;
        }
        __syncthreads();

        float* dbase = dashp + ((size_t)bh * NSEQ + chunk * 1024 + s * 128) * MPAD;
#pragma unroll
        for (int rb = 0; rb < 2; rb++) {
            unsigned int aHiR = sb + SM_AHI +
                (unsigned)((r0w + rb * 16 + a_row) * BROW + a_k8 * 2);
            unsigned int aLoR = aHiR + (SM_ALO - SM_AHI);
            float c[9][4];
#pragma unroll
            for (int nb = 0; nb < 9; nb++)
#pragma unroll
                for (int q = 0; q < 4; q++) c[nb][q] = 0.f;

#pragma unroll
            for (int kk = 0; kk < 4; kk++) {
                unsigned int ah[4], al[4];
                LDM_X4(ah, aHiR + kk * 32);
                LDM_X4(al, aLoR + kk * 32);
#pragma unroll
                for (int nb = 0; nb < 9; nb++) {
                    unsigned int bh0, bh1, bl0, bl1;
                    LDM_X2(bh0, bh1, bHiP + nb * 8 * BROW + kk * 32);
                    LDM_X2(bl0, bl1, bLoP + nb * 8 * BROW + kk * 32);
                    MMA_BF16(c[nb], ah, bh0, bh1);
                    MMA_BF16(c[nb], ah, bl0, bl1);
                    MMA_BF16(c[nb], al, bh0, bh1);
                }
            }
            int rA = r0w + rb * 16 + g;
#pragma unroll
            for (int nb = 0; nb < 9; nb++) {
                int n = n0w + nb * 8 + tc * 2;
                if (n < MPAD) {
                    *(float2*)(dbase + (size_t)rA * MPAD + n) = make_float2(c[nb][0], c[nb][1]);
                    *(float2*)(dbase + (size_t)(rA + 8) * MPAD + n) = make_float2(c[nb][2], c[nb][3]);
                }
                if (isK) {
                    if (n < MDIM) maxv = fmaxf(maxv, fmaxf(c[nb][0], c[nb][2]));
                    if (n + 1 < MDIM) maxv = fmaxf(maxv, fmaxf(c[nb][1], c[nb][3]));
                }
            }
        }
    }

    if (isK) {
#pragma unroll
        for (int o = 16; o; o >>= 1) maxv = fmaxf(maxv, __shfl_xor_sync(0xffffffffu, maxv, o));
        if (lid == 0) atomicMax(&red, fenc(maxv));
        __syncthreads();
        if (tid == 0) atomicMax(&g_stab_bits, red);
    }
}

// =======================================================================
// context_mma (unchanged, R12-passing): C[m][e] via bf16x3 mma.
// =======================================================================
#define KROWB 560
#define VROWB 176
#define SM2_KH 0
#define SM2_KL 17920
#define SM2_VH 35840
#define SM2_VL 41472
#define SM2_TOTAL 47104

__global__ void __launch_bounds__(576, 1)
context_mma_kernel(const float* __restrict__ vv) {
    extern __shared__ char smc[];
    unsigned int sb = smem_u32(smc);
    int tid = threadIdx.x, wid = tid >> 5, lid = tid & 31;
    int g = lid >> 2, tc = lid & 3;
    int bh = 31 - blockIdx.y;
    int row0b = (7 - (int)blockIdx.x) * 512;

    const float* dbase = g_kdash + ((size_t)bh * NSEQ + row0b) * MPAD;
    const float* diagb = g_kdiag + bh * NSEQ + row0b;
    const float* vbase = vv + ((size_t)bh * NSEQ + row0b) * DDIM;
    const float stab = fdec(*(volatile unsigned int*)&g_stab_bits);
    const float c1 = RATIO / (float)NSEQ;

    for (int t = tid; t < 32 * 24; t += 576) {
        int r = t / 24, cc = 64 + t % 24;
        *(unsigned short*)(smc + SM2_VH + r * VROWB + cc * 2) = 0;
        *(unsigned short*)(smc + SM2_VL + r * VROWB + cc * 2) = 0;
    }
    __syncthreads();
    for (int t = tid; t < 32; t += 576)
        *(unsigned short*)(smc + SM2_VH + t * VROWB + 64 * 2) = 0x3F80;  // bf16 1.0

    int a_krow = ((lid >> 4) & 1) * 8 + (lid & 7);
    int a_mcol = ((lid >> 3) & 1) * 8;
    int b_krow = (lid & 7) + ((lid >> 3) & 1) * 8;
    unsigned int aH = sb + SM2_KH + (unsigned)(a_krow * KROWB);
    unsigned int aL = sb + SM2_KL + (unsigned)(a_krow * KROWB);
    unsigned int bH = sb + SM2_VH + (unsigned)(b_krow * VROWB);
    unsigned int bL = sb + SM2_VL + (unsigned)(b_krow * VROWB);

    int mt = wid;
    int active = (mt < 17);

    float c[9][4];
#pragma unroll
    for (int nt = 0; nt < 9; nt++)
#pragma unroll
        for (int q = 0; q < 4; q++) c[nt][q] = 0.f;

    for (int s = 0; s < 16; s++) {
        __syncthreads();
        {
            const float4* vsrc = (const float4*)(vbase + (size_t)s * 32 * DDIM);
            for (int t = tid; t < 512; t += 576) {
                int r = t >> 4, e4 = t & 15;
                float4 v = vsrc[t];
                unsigned int h0, l0, h1, l1;
                split2(v.x, v.y, h0, l0);
                split2(v.z, v.w, h1, l1);
                *(uint2*)(smc + SM2_VH + r * VROWB + e4 * 8) = make_uint2(h0, h1);
                *(uint2*)(smc + SM2_VL + r * VROWB + e4 * 8) = make_uint2(l0, l1);
            }
        }
        {
            for (int t = tid; t < 2176; t += 576) {
                int r = t / 68, m4 = t - r * 68;
                float4 dd = *(const float4*)(dbase + (size_t)(s * 32 + r) * MPAD + m4 * 4);
                float dg = diagb[s * 32 + r] + stab;
                int m = m4 * 4;
                float4 o;
                o.x = (m + 0 < MDIM) ? c1 * (__expf(dd.x - dg) + KEPS) : 0.f;
                o.y = (m + 1 < MDIM) ? c1 * (__expf(dd.y - dg) + KEPS) : 0.f;
                o.z = (m + 2 < MDIM) ? c1 * (__expf(dd.z - dg) + KEPS) : 0.f;
                o.w = (m + 3 < MDIM) ? c1 * (__expf(dd.w - dg) + KEPS) : 0.f;
                unsigned int h0, l0, h1, l1;
                split2(o.x, o.y, h0, l0);
                split2(o.z, o.w, h1, l1);
                *(uint2*)(smc + SM2_KH + r * KROWB + m4 * 8) = make_uint2(h0, h1);
                *(uint2*)(smc + SM2_KL + r * KROWB + m4 * 8) = make_uint2(l0, l1);
            }
        }
        __syncthreads();

        if (active) {
#pragma unroll
            for (int kk = 0; kk < 2; kk++) {
                unsigned int ka = kk * 16 * KROWB;
                unsigned int a0h[4], a0l[4];
                LDM_X4T(a0h, aH + ka + (mt * 16 + a_mcol) * 2);
                LDM_X4T(a0l, aL + ka + (mt * 16 + a_mcol) * 2);
                unsigned int kb = kk * 16 * VROWB;
#pragma unroll
                for (int nt = 0; nt < 9; nt++) {
                    unsigned int bh0, bh1, bl0, bl1;
                    LDM_X2T(bh0, bh1, bH + kb + nt * 16);
                    LDM_X2T(bl0, bl1, bL + kb + nt * 16);
                    MMA_BF16(c[nt], a0h, bh0, bh1);
                    MMA_BF16(c[nt], a0h, bl0, bl1);
                    MMA_BF16(c[nt], a0l, bh0, bh1);
                }
            }
        }
    }

    if (active) {
        float* gCT = g_CT + (size_t)bh * EROWS * MPAD;
        int m0 = mt * 16 + g, m1 = m0 + 8;
#pragma unroll
        for (int nt = 0; nt < 9; nt++) {
            int e0 = nt * 8 + tc * 2;
            if (e0 < ECOLS) {
                if (m0 < MDIM) atomicAdd(&gCT[(size_t)e0 * MPAD + m0], c[nt][0]);
                if (m1 < MDIM) atomicAdd(&gCT[(size_t)e0 * MPAD + m1], c[nt][2]);
            }
            if (e0 + 1 < ECOLS) {
                if (m0 < MDIM) atomicAdd(&gCT[(size_t)(e0 + 1) * MPAD + m0], c[nt][1]);
                if (m1 < MDIM) atomicAdd(&gCT[(size_t)(e0 + 1) * MPAD + m1], c[nt][3]);
            }
        }
    }
}

// =======================================================================
// out_mma: out = D_inv * qp @ C via bf16x3 mma. A = qp[row][m] (K=272+8pad),
// B = C^T[e][m] rows (N=80 incl e=64 ones/k_mean row -> denominator from
// the SAME mma). grid (4,32) = 128 blocks (1 wave), 640 threads / 20 warps,
// warp = (mb in 0..1) x (nt in 0..9). 32 subtiles of 32 rows.
// =======================================================================
#define OROWB 560
#define SM3_CH 0
#define SM3_CL 44800
#define SM3_QH 89600
#define SM3_QL 107520
#define SM3_QD 125440          // qdash f32 staging [32][272]; aliased outbuf [32][80]
#define SM3_RMAX 160256
#define SM3_TOTAL 160512

__global__ void __launch_bounds__(640, 1)
out_mma_kernel(float* __restrict__ out) {
    extern __shared__ char smc[];
    unsigned int sb = smem_u32(smc);
    int tid = threadIdx.x, wid = tid >> 5, lid = tid & 31;
    int g = lid >> 2, tc = lid & 3;
    int bh = 31 - (int)blockIdx.y;            // reversed (qdash L2 reuse)
    int row0b = (3 - (int)blockIdx.x) * 1024;

    {   // build C bf16 hi/lo tiles [80 e-rows][280 m-cols]; pads zero
        const float* gCT = g_CT + (size_t)bh * EROWS * MPAD;
        for (int t = tid; t < 80 * 70; t += 640) {
            int e = t / 70, m4 = t % 70;
            float4 v = make_float4(0.f, 0.f, 0.f, 0.f);
            if (e < ECOLS && m4 < 68) v = *(const float4*)(gCT + (size_t)e * MPAD + m4 * 4);
            unsigned int h0, l0, h1, l1;
            split2(v.x, v.y, h0, l0);
            split2(v.z, v.w, h1, l1);
            *(uint2*)(smc + SM3_CH + e * OROWB + m4 * 8) = make_uint2(h0, h1);
            *(uint2*)(smc + SM3_CL + e * OROWB + m4 * 8) = make_uint2(l0, l1);
        }
    }
    const float* dbase = g_qdash + ((size_t)bh * NSEQ + row0b) * MPAD;
    const float* diagb = g_qdiag + bh * NSEQ + row0b;
    float* obase = out + ((size_t)bh * NSEQ + row0b) * DDIM;
    float* rmax = (float*)(smc + SM3_RMAX);
    float* qdF = (float*)(smc + SM3_QD);
    float4* qd4 = (float4*)(smc + SM3_QD);
    float* ob = (float*)(smc + SM3_QD);       // alias: dead after exp phase

    int mb = wid & 1, nt = wid >> 1;          // warp tile
    int a_row = ((lid >> 3) & 1) * 8 + (lid & 7);
    int a_k8  = ((lid >> 4) & 1) * 8;
    int b_row = lid & 7;
    int b_k8  = ((lid >> 3) & 1) * 8;
    unsigned int aH0 = sb + SM3_QH + (unsigned)((mb * 16 + a_row) * OROWB + a_k8 * 2);
    unsigned int aL0 = aH0 + (SM3_QL - SM3_QH);
    unsigned int bH0 = sb + SM3_CH + (unsigned)((nt * 8 + b_row) * OROWB + b_k8 * 2);
    unsigned int bL0 = bH0 + (SM3_CL - SM3_CH);
    __syncthreads();

    for (int s = 0; s < 32; s++) {
        {   // 1. qdash f32 tile -> smem (contiguous [32][272])
            for (int t = tid; t < 2176; t += 640) {
                int r = t / 68, m4 = t - r * 68;
                qd4[r * 68 + m4] = *(const float4*)(dbase + (size_t)(s * 32 + r) * MPAD + m4 * 4);
            }
        }
        __syncthreads();
        if (tid < 256) {   // 2. per-row max
            int r = tid >> 3, part = tid & 7;
            float mv = -INFINITY;
            for (int m = part; m < MDIM; m += 8) mv = fmaxf(mv, qdF[r * 272 + m]);
            mv = fmaxf(mv, __shfl_xor_sync(0xffffffffu, mv, 1));
            mv = fmaxf(mv, __shfl_xor_sync(0xffffffffu, mv, 2));
            mv = fmaxf(mv, __shfl_xor_sync(0xffffffffu, mv, 4));
            if (part == 0) rmax[r] = mv;
        }
        __syncthreads();
        {   // 3. exp + split -> qp hi/lo (280 cols; pads zero)
            for (int t = tid; t < 32 * 70; t += 640) {
                int r = t / 70, m4 = t % 70;
                float4 dd = (m4 < 68) ? qd4[r * 68 + m4] : make_float4(0.f, 0.f, 0.f, 0.f);
                float dg = diagb[s * 32 + r] + rmax[r];
                int m = m4 * 4;
                float4 o;
                o.x = (m + 0 < MDIM) ? RATIO * (__expf(dd.x - dg) + KEPS) : 0.f;
                o.y = (m + 1 < MDIM) ? RATIO * (__expf(dd.y - dg) + KEPS) : 0.f;
                o.z = (m + 2 < MDIM) ? RATIO * (__expf(dd.z - dg) + KEPS) : 0.f;
                o.w = (m + 3 < MDIM) ? RATIO * (__expf(dd.w - dg) + KEPS) : 0.f;
                unsigned int h0, l0, h1, l1;
                split2(o.x, o.y, h0, l0);
                split2(o.z, o.w, h1, l1);
                *(uint2*)(smc + SM3_QH + r * OROWB + m4 * 8) = make_uint2(h0, h1);
                *(uint2*)(smc + SM3_QL + r * OROWB + m4 * 8) = make_uint2(l0, l1);
            }
        }
        __syncthreads();
        {   // 4. mma: M=32 (mb), N=80 (nt), K=280 (17 k16 steps cover 272; pads zero)
            float c[4];
            c[0] = c[1] = c[2] = c[3] = 0.f;
#pragma unroll
            for (int kk = 0; kk < 17; kk++) {
                unsigned int ah[4], al[4];
                LDM_X4(ah, aH0 + kk * 32);
                LDM_X4(al, aL0 + kk * 32);
                unsigned int bh0, bh1, bl0, bl1;
                LDM_X2(bh0, bh1, bH0 + kk * 32);
                LDM_X2(bl0, bl1, bL0 + kk * 32);
                MMA_BF16(c, ah, bh0, bh1);
                MMA_BF16(c, ah, bl0, bl1);
                MMA_BF16(c, al, bh0, bh1);
            }
            // fragments -> outbuf [32][80] f32 (qdash region now dead)
            int r0f = mb * 16 + g;
            int cidx = nt * 8 + tc * 2;
            ob[r0f * 80 + cidx] = c[0];
            ob[r0f * 80 + cidx + 1] = c[1];
            ob[(r0f + 8) * 80 + cidx] = c[2];
            ob[(r0f + 8) * 80 + cidx + 1] = c[3];
        }
        __syncthreads();
        {   // 5. divide by den (col 64) and write out
            for (int t = tid; t < 512; t += 640) {
                int r = t >> 4, e4 = t & 15;
                float di = 1.0f / ob[r * 80 + 64];
                float4 o;
                o.x = ob[r * 80 + e4 * 4 + 0] * di;
                o.y = ob[r * 80 + e4 * 4 + 1] * di;
                o.z = ob[r * 80 + e4 * 4 + 2] * di;
                o.w = ob[r * 80 + e4 * 4 + 3] * di;
                *(float4*)(obase + (size_t)(s * 32 + r) * DDIM + e4 * 4) = o;
            }
        }
        __syncthreads();
    }
}

// =======================================================================
extern "C" void kernel_launch(void* const* d_in, const int* in_sizes, int n_in,
                              void* d_out, int out_size) {
    int pidx = -1;
    for (int i = 0; i < n_in; i++) if (in_sizes[i] == MDIM * DDIM) pidx = i;
    const float* rest[3] = {nullptr, nullptr, nullptr};
    int rc = 0;
    for (int i = 0; i < n_in && rc < 3; i++) {
        if (i == pidx) continue;
        rest[rc++] = (const float*)d_in[i];
    }
    const float* q = rest[0];
    const float* k = rest[1];
    const float* v = rest[2];
    const float* proj = (const float*)d_in[pidx];
    float* out = (float*)d_out;

    cudaFuncSetAttribute(dash_mma_kernel,    cudaFuncAttributeMaxDynamicSharedMemorySize, SM_DASH_TOTAL);
    cudaFuncSetAttribute(context_mma_kernel, cudaFuncAttributeMaxDynamicSharedMemorySize, SM2_TOTAL);
    cudaFuncSetAttribute(out_mma_kernel,     cudaFuncAttributeMaxDynamicSharedMemorySize, SM3_TOTAL);

    init_kernel<<<512, 256>>>();
    // order: each scratch tensor consumed right after production (L2 reuse)
    dash_mma_kernel<<<BH * 4, 512, SM_DASH_TOTAL>>>(k, proj, 1);
    context_mma_kernel<<<dim3(8, 32), 576, SM2_TOTAL>>>(v);
    dash_mma_kernel<<<BH * 4, 512, SM_DASH_TOTAL>>>(q, proj, 0);
    out_mma_kernel<<<dim3(4, 32), 640, SM3_TOTAL>>>(out);
}